// round 14
// baseline (speedup 1.0000x reference)
#include <cuda_runtime.h>
#include <cuda_fp16.h>
#include <cstdint>
#include <cstddef>

#define NTOK 16384
#define DIM  2048
#define FFD  5632

// ---------------- scratch: static device globals (no allocation) ------------
__device__ __align__(1024) __half g_xp [(size_t)2 * NTOK * DIM];
__device__ __align__(1024) __half g_h  [(size_t)2 * NTOK * FFD];
__device__ __align__(1024) __half g_wgH[(size_t)2 * DIM * FFD];  // [D,FF] n-major
__device__ __align__(1024) __half g_wuH[(size_t)2 * DIM * FFD];  // [D,FF] n-major
__device__ __align__(1024) __half g_wdH[(size_t)2 * FFD * DIM];  // [FF,D] n-major
__device__ int g_count[2];
__device__ int g_rowtok[2 * NTOK];

// ---------------- PTX helpers (compute_103-safe: no tcgen05) -----------------
__device__ __forceinline__ uint32_t smem_to_u32(const void* p) {
    uint32_t a;
    asm("{ .reg .u64 t; cvta.to.shared.u64 t, %1; cvt.u32.u64 %0, t; }"
        : "=r"(a) : "l"(p));
    return a;
}

__device__ __forceinline__ void ldsm_x4(uint32_t& r0, uint32_t& r1,
                                        uint32_t& r2, uint32_t& r3,
                                        uint32_t addr) {
    asm volatile("ldmatrix.sync.aligned.m8n8.x4.shared.b16 {%0,%1,%2,%3}, [%4];"
                 : "=r"(r0), "=r"(r1), "=r"(r2), "=r"(r3) : "r"(addr));
}

// transposed load: n-major [K,N] smem tile -> K-major B fragments
__device__ __forceinline__ void ldsm_x4t(uint32_t& r0, uint32_t& r1,
                                         uint32_t& r2, uint32_t& r3,
                                         uint32_t addr) {
    asm volatile("ldmatrix.sync.aligned.m8n8.x4.trans.shared.b16 {%0,%1,%2,%3}, [%4];"
                 : "=r"(r0), "=r"(r1), "=r"(r2), "=r"(r3) : "r"(addr));
}

__device__ __forceinline__ void mma16816(float* c, const uint32_t* a,
                                         uint32_t b0, uint32_t b1) {
    asm volatile(
        "mma.sync.aligned.m16n8k16.row.col.f32.f16.f16.f32 "
        "{%0,%1,%2,%3}, {%4,%5,%6,%7}, {%8,%9}, {%0,%1,%2,%3};"
        : "+f"(c[0]), "+f"(c[1]), "+f"(c[2]), "+f"(c[3])
        : "r"(a[0]), "r"(a[1]), "r"(a[2]), "r"(a[3]), "r"(b0), "r"(b1));
}

// bulk async copy: one row per instruction (UBLKCP), mbarrier completion
__device__ __forceinline__ void cp_bulk(uint32_t dst, const void* src,
                                        uint32_t bytes, uint32_t mbar) {
    asm volatile(
        "cp.async.bulk.shared::cluster.global.mbarrier::complete_tx::bytes "
        "[%0], [%1], %2, [%3];"
        :: "r"(dst), "l"(src), "r"(bytes), "r"(mbar) : "memory");
}

#define MBARRIER_INIT(mbar, count) \
    asm volatile("mbarrier.init.shared.b64 [%0], %1;" \
        :: "r"((uint32_t)(mbar)), "r"((uint32_t)(count)) : "memory")
#define MBARRIER_EXPECT_TX(mbar, bytes) \
    asm volatile("mbarrier.arrive.expect_tx.shared.b64 _, [%0], %1;" \
        :: "r"((uint32_t)(mbar)), "r"((uint32_t)(bytes)) : "memory")

#define MBARRIER_WAIT_PARITY(mbar_addr, phase_parity) do {                         \
    uint32_t _mbar = (uint32_t)(mbar_addr);                                        \
    uint32_t _par  = (uint32_t)(phase_parity);                                     \
    uint32_t _done;                                                                \
    asm volatile(                                                                  \
        "{\n\t.reg .pred p;\n\t"                                                   \
        "mbarrier.try_wait.parity.acquire.cta.shared::cta.b64 p, [%1], %2;\n\t"    \
        "selp.b32 %0, 1, 0, p;\n\t}"                                               \
        : "=r"(_done) : "r"(_mbar), "r"(_par) : "memory");                         \
    if (!_done) {                                                                  \
        asm volatile(                                                              \
            "{\n\t.reg .pred P1;\n\t"                                              \
            "WAIT_LOOP_%=:\n\t"                                                    \
            "mbarrier.try_wait.parity.acquire.cta.shared::cta.b64 P1, [%0], %1, 0x989680;\n\t" \
            "@P1 bra.uni WAIT_DONE_%=;\n\t"                                        \
            "bra.uni WAIT_LOOP_%=;\n\t"                                            \
            "WAIT_DONE_%=:\n\t}"                                                   \
            :: "r"(_mbar), "r"(_par) : "memory");                                  \
    }                                                                              \
} while (0)

__device__ __forceinline__ float silu(float x) {
    return x * __fdividef(1.0f, 1.0f + __expf(-x));
}

// supergroup swizzle: G=8 n-tiles, n-fast within group -> L2-resident wave
__device__ __forceinline__ void tilemap(int bx, int mtiles, int ntiles,
                                        int& m, int& n) {
    const int G = 8;
    int full = (ntiles / G) * G;
    if (bx < full * mtiles) {
        int per = G * mtiles;
        int sg = bx / per, rem = bx % per;
        n = sg * G + rem % G;
        m = rem / G;
    } else {
        int rem = bx - full * mtiles;
        int w = ntiles - full;
        n = full + rem % w;
        m = rem / w;
    }
}

// ---------------- small kernels ----------------------------------------------
__global__ void zero_counters_kernel() {
    if (threadIdx.x < 2) g_count[threadIdx.x] = 0;
}

__global__ void route_gather_kernel(const float* __restrict__ x,
                                    const int* __restrict__ mask) {
    __shared__ int s_row;
    int t = blockIdx.x;
    if (threadIdx.x == 0) {
        int e = (mask[t] != 0) ? 1 : 0;
        int slot = atomicAdd(&g_count[e], 1);
        g_rowtok[e * NTOK + slot] = t;
        s_row = e * NTOK + slot;
    }
    __syncthreads();
    int row = s_row;
    const float4* src = reinterpret_cast<const float4*>(x + (size_t)t * DIM);
    __half2* dst = reinterpret_cast<__half2*>(g_xp + (size_t)row * DIM);
    for (int i = threadIdx.x; i < DIM / 4; i += blockDim.x) {
        float4 v = src[i];
        dst[2 * i + 0] = __floats2half2_rn(v.x, v.y);
        dst[2 * i + 1] = __floats2half2_rn(v.z, v.w);
    }
}

// fused fp32 -> fp16 convert of all three weight tensors (same layout)
#define NW4 ((int)(2 * (size_t)DIM * FFD / 4))
__global__ void convert_all_kernel(const float* __restrict__ wg,
                                   const float* __restrict__ wu,
                                   const float* __restrict__ wd) {
    int stride = gridDim.x * blockDim.x;
    for (int i = blockIdx.x * blockDim.x + threadIdx.x; i < 3 * NW4; i += stride) {
        int seg = i / NW4, rem = i - seg * NW4;
        const float* src = (seg == 0) ? wg : (seg == 1) ? wu : wd;
        __half* dst = (seg == 0) ? g_wgH : (seg == 1) ? g_wuH : g_wdH;
        float4 v = reinterpret_cast<const float4*>(src)[rem];
        __half2* d = reinterpret_cast<__half2*>(dst) + 2 * (size_t)rem;
        d[0] = __floats2half2_rn(v.x, v.y);
        d[1] = __floats2half2_rn(v.z, v.w);
    }
}

// ---------------- GEMM tiling ------------------------------------------------
// CTA tile 128(M) x 128(N). A: K-major smem rows (SRA=72 halves, BK=64).
// B: n-major smem rows (SRB=136 halves), ldmatrix.trans. 3-stage pipeline,
// loads via per-row cp.async.bulk + mbarrier expect_tx/complete_tx.
#define BM   128
#define BN   128
#define BK   64
#define SRA  72
#define SRB  136
#define STGA (BM * SRA)        // 9216 halves
#define STGB (BK * SRB)        // 8704 halves
#define STG1 (STGA + 2 * STGB) // gemm1 stage: 26624 halves = 53248 B
#define STG2 (STGA + STGB)     // gemm2 stage: 17920 halves = 35840 B
#define SMEM1 (3 * STG1 * 2)   // 159744 B
#define SMEM2 (3 * STG2 * 2)   // 107520 B
#define TX1 (BM * BK * 2 + 2 * BK * BN * 2)  // 49152 B per gemm1 stage
#define TX2 (BM * BK * 2 + BK * BN * 2)      // 32768 B per gemm2 stage

// ---------------- GEMM1: gate+up fused, h = silu(g)*u ------------------------
__global__ __launch_bounds__(512, 1) void gemm1_kernel() {
    extern __shared__ __half sm[];
    __shared__ __align__(16) unsigned long long s_mb[3];

    int tid = threadIdx.x, wid = tid >> 5, lane = tid & 31;
    int e = blockIdx.y, cnt = g_count[e];
    int mt_i, nt_i;
    tilemap(blockIdx.x, NTOK / BM, FFD / BN, mt_i, nt_i);
    int m0 = mt_i * BM;
    if (m0 >= cnt) return;
    int n0 = nt_i * BN;
    int wm = wid & 3, wn = wid >> 2;   // 4M x 4N warps, warp tile 32x32

    const __half* Ab = g_xp  + (size_t)(e * NTOK + m0) * DIM;
    const __half* Bg = g_wgH + (size_t)e * DIM * FFD + n0;
    const __half* Bu = g_wuH + (size_t)e * DIM * FFD + n0;
    uint32_t sbase = smem_to_u32(sm);
    uint32_t mb0 = smem_to_u32(&s_mb[0]);

    if (tid == 0) {
        MBARRIER_INIT(mb0,      1);
        MBARRIER_INIT(mb0 + 8,  1);
        MBARRIER_INIT(mb0 + 16, 1);
    }
    __syncthreads();

    float cg[2][4][4] = {}, cu[2][4][4] = {};

    int gq = lane >> 3, lr = lane & 7;
    int aRow = wm * 32 + lr + (gq & 1) * 8;            // + mt*16
    int aCol = (gq >> 1) * 8;                          // + ks*16
    uint32_t aoff = (uint32_t)(aRow * SRA + aCol) * 2;
    int bR = lr + (gq & 1) * 8;                        // k row, + ks*16
    int bC = wn * 32 + ((gq >> 1) & 1) * 8;            // n col, + j*16
    uint32_t boff = (uint32_t)(bR * SRB + bC) * 2;

    // loader: 256 bulk row-copies (A 128 x 128B, Bg 64 x 256B, Bu 64 x 256B)
    auto issue = [&](int it, int s) {
        uint32_t db = sbase + (uint32_t)(s * STG1) * 2;
        uint32_t mb = mb0 + s * 8;
        if (tid == 0) MBARRIER_EXPECT_TX(mb, TX1);
        if (tid < 128) {
            cp_bulk(db + (uint32_t)(tid * SRA) * 2,
                    Ab + (size_t)tid * DIM + it * BK, BK * 2, mb);
        } else if (tid < 192) {
            int r = tid - 128;
            cp_bulk(db + (uint32_t)(STGA + r * SRB) * 2,
                    Bg + (size_t)(it * BK + r) * FFD, BN * 2, mb);
        } else if (tid < 256) {
            int r = tid - 192;
            cp_bulk(db + (uint32_t)(STGA + STGB + r * SRB) * 2,
                    Bu + (size_t)(it * BK + r) * FFD, BN * 2, mb);
        }
    };

    issue(0, 0);
    issue(1, 1);

    const int KT = DIM / BK;  // 32
    for (int it = 0; it < KT; ++it) {
        int s = it % 3;
        MBARRIER_WAIT_PARITY(mb0 + s * 8, (it / 3) & 1);
        __syncthreads();                 // all consumers done with stage (it-1)%3
        if (it + 2 < KT) issue(it + 2, (it + 2) % 3);

        uint32_t s0 = sbase + (uint32_t)(s * STG1) * 2;
        #pragma unroll
        for (int ks = 0; ks < 4; ++ks) {
            uint32_t a[2][4], b[2][4];
            #pragma unroll
            for (int mt = 0; mt < 2; ++mt)
                ldsm_x4(a[mt][0], a[mt][1], a[mt][2], a[mt][3],
                        s0 + aoff + (uint32_t)(mt * 16 * SRA + ks * 16) * 2);
            // gate
            uint32_t gb = s0 + (uint32_t)(STGA + ks * 16 * SRB) * 2 + boff;
            #pragma unroll
            for (int j = 0; j < 2; ++j)
                ldsm_x4t(b[j][0], b[j][1], b[j][2], b[j][3], gb + j * 32);
            #pragma unroll
            for (int mt = 0; mt < 2; ++mt)
                #pragma unroll
                for (int j = 0; j < 2; ++j) {
                    mma16816(cg[mt][j * 2 + 0], a[mt], b[j][0], b[j][1]);
                    mma16816(cg[mt][j * 2 + 1], a[mt], b[j][2], b[j][3]);
                }
            // up
            uint32_t ub = gb + (uint32_t)STGB * 2;
            #pragma unroll
            for (int j = 0; j < 2; ++j)
                ldsm_x4t(b[j][0], b[j][1], b[j][2], b[j][3], ub + j * 32);
            #pragma unroll
            for (int mt = 0; mt < 2; ++mt)
                #pragma unroll
                for (int j = 0; j < 2; ++j) {
                    mma16816(cu[mt][j * 2 + 0], a[mt], b[j][0], b[j][1]);
                    mma16816(cu[mt][j * 2 + 1], a[mt], b[j][2], b[j][3]);
                }
        }
    }

    // epilogue: h = silu(g)*u, fp16 half2 stores
    __half* hout = g_h + (size_t)(e * NTOK + m0) * FFD + n0;
    int rb = wm * 32 + (lane >> 2);
    int cb = wn * 32 + (lane & 3) * 2;
    #pragma unroll
    for (int mt = 0; mt < 2; ++mt)
        #pragma unroll
        for (int nt = 0; nt < 4; ++nt) {
            float* pg = cg[mt][nt];
            float* pu = cu[mt][nt];
            int r = rb + mt * 16, c = cb + nt * 8;
            *reinterpret_cast<__half2*>(hout + (size_t)r * FFD + c) =
                __floats2half2_rn(silu(pg[0]) * pu[0], silu(pg[1]) * pu[1]);
            *reinterpret_cast<__half2*>(hout + (size_t)(r + 8) * FFD + c) =
                __floats2half2_rn(silu(pg[2]) * pu[2], silu(pg[3]) * pu[3]);
        }
}

// ---------------- GEMM2: out = h @ Wd, scattered to token order --------------
__global__ __launch_bounds__(256, 2) void gemm2_kernel(float* __restrict__ out) {
    extern __shared__ __half sm[];
    __shared__ __align__(16) unsigned long long s_mb[3];
    __shared__ int srt[BM];

    int tid = threadIdx.x, wid = tid >> 5, lane = tid & 31;
    int e = blockIdx.y, cnt = g_count[e];
    int mt_i, nt_i;
    tilemap(blockIdx.x, NTOK / BM, DIM / BN, mt_i, nt_i);
    int m0 = mt_i * BM;
    if (m0 >= cnt) return;
    int n0 = nt_i * BN;
    int wm = wid & 3, wn = wid >> 2;   // 4M x 2N warps, warp tile 32x64

    for (int i = tid; i < BM; i += 256) {
        int rr = m0 + i;
        srt[i] = (rr < cnt) ? g_rowtok[e * NTOK + rr] : -1;
    }

    const __half* Ab = g_h   + (size_t)(e * NTOK + m0) * FFD;
    const __half* Bb = g_wdH + (size_t)e * FFD * DIM + n0;
    uint32_t sbase = smem_to_u32(sm);
    uint32_t mb0 = smem_to_u32(&s_mb[0]);

    if (tid == 0) {
        MBARRIER_INIT(mb0,      1);
        MBARRIER_INIT(mb0 + 8,  1);
        MBARRIER_INIT(mb0 + 16, 1);
    }
    __syncthreads();

    float cc[2][8][4] = {};

    int gq = lane >> 3, lr = lane & 7;
    int aRow = wm * 32 + lr + (gq & 1) * 8;
    int aCol = (gq >> 1) * 8;
    uint32_t aoff = (uint32_t)(aRow * SRA + aCol) * 2;
    int bR = lr + (gq & 1) * 8;
    int bC = wn * 64 + ((gq >> 1) & 1) * 8;
    uint32_t boff = (uint32_t)(bR * SRB + bC) * 2;

    // loader: 192 bulk row-copies (A 128 x 128B, B 64 x 256B)
    auto issue = [&](int it, int s) {
        uint32_t db = sbase + (uint32_t)(s * STG2) * 2;
        uint32_t mb = mb0 + s * 8;
        if (tid == 0) MBARRIER_EXPECT_TX(mb, TX2);
        if (tid < 128) {
            cp_bulk(db + (uint32_t)(tid * SRA) * 2,
                    Ab + (size_t)tid * FFD + it * BK, BK * 2, mb);
        } else if (tid < 192) {
            int r = tid - 128;
            cp_bulk(db + (uint32_t)(STGA + r * SRB) * 2,
                    Bb + (size_t)(it * BK + r) * DIM, BN * 2, mb);
        }
    };

    issue(0, 0);
    issue(1, 1);

    const int KT = FFD / BK;  // 88
    for (int it = 0; it < KT; ++it) {
        int s = it % 3;
        MBARRIER_WAIT_PARITY(mb0 + s * 8, (it / 3) & 1);
        __syncthreads();
        if (it + 2 < KT) issue(it + 2, (it + 2) % 3);

        uint32_t s0 = sbase + (uint32_t)(s * STG2) * 2;
        #pragma unroll
        for (int ks = 0; ks < 4; ++ks) {
            uint32_t a[2][4], b[4][4];
            #pragma unroll
            for (int mt = 0; mt < 2; ++mt)
                ldsm_x4(a[mt][0], a[mt][1], a[mt][2], a[mt][3],
                        s0 + aoff + (uint32_t)(mt * 16 * SRA + ks * 16) * 2);
            uint32_t bb = s0 + (uint32_t)(STGA + ks * 16 * SRB) * 2 + boff;
            #pragma unroll
            for (int j = 0; j < 4; ++j)
                ldsm_x4t(b[j][0], b[j][1], b[j][2], b[j][3], bb + j * 32);
            #pragma unroll
            for (int mt = 0; mt < 2; ++mt)
                #pragma unroll
                for (int j = 0; j < 4; ++j) {
                    mma16816(cc[mt][j * 2 + 0], a[mt], b[j][0], b[j][1]);
                    mma16816(cc[mt][j * 2 + 1], a[mt], b[j][2], b[j][3]);
                }
        }
    }

    // epilogue: scatter rows to original token positions (fp32 float2)
    int rb = wm * 32 + (lane >> 2);
    int cb = n0 + wn * 64 + (lane & 3) * 2;
    #pragma unroll
    for (int mt = 0; mt < 2; ++mt)
        #pragma unroll
        for (int nt = 0; nt < 8; ++nt) {
            float* p = cc[mt][nt];
            int rl = rb + mt * 16;
            int c = cb + nt * 8;
            int t0 = srt[rl];
            if (t0 >= 0)
                *reinterpret_cast<float2*>(out + (size_t)t0 * DIM + c) =
                    make_float2(p[0], p[1]);
            int t1 = srt[rl + 8];
            if (t1 >= 0)
                *reinterpret_cast<float2*>(out + (size_t)t1 * DIM + c) =
                    make_float2(p[2], p[3]);
        }
}

// ---------------- launch ------------------------------------------------------
extern "C" void kernel_launch(void* const* d_in, const int* in_sizes, int n_in,
                              void* d_out, int out_size) {
    const float* hs   = (const float*)d_in[0];
    const int*   mask = (const int*)d_in[1];
    const float* wg   = (const float*)d_in[2];
    const float* wu   = (const float*)d_in[3];
    const float* wd   = (const float*)d_in[4];
    float* out = (float*)d_out;
    (void)in_sizes; (void)n_in; (void)out_size;

    cudaFuncSetAttribute(gemm1_kernel,
                         cudaFuncAttributeMaxDynamicSharedMemorySize, SMEM1);
    cudaFuncSetAttribute(gemm2_kernel,
                         cudaFuncAttributeMaxDynamicSharedMemorySize, SMEM2);

    zero_counters_kernel<<<1, 32>>>();
    route_gather_kernel<<<NTOK, 128>>>(hs, mask);
    convert_all_kernel<<<8192, 256>>>(wg, wu, wd);

    dim3 g1((NTOK / BM) * (FFD / BN), 2);
    gemm1_kernel<<<g1, 512, SMEM1>>>();

    dim3 g2((NTOK / BM) * (DIM / BN), 2);
    gemm2_kernel<<<g2, 256, SMEM2>>>(out);
}